// round 7
// baseline (speedup 1.0000x reference)
#include <cuda_runtime.h>
#include <cuda_bf16.h>
#include <cstdint>

#define T_TOK 8192
#define D_IN  1024
#define D_OUT 1024
#define NE    8
#define TM    128
#define TN    128
#define BK    32
#define KSTAGES (D_IN / BK)          // 32
#define NST   3
#define ROWB  48                     // 32 int8 + 16B pad (conflict-free)
#define TILEB (128 * ROWB)           // 6144
#define STGB  (4 * TILEB)            // 24576: Ah|Al|Bh|Bl
#define OFF_STOK (NST * STGB)        // 73728
#define OFF_BIAS (OFF_STOK + 512)
#define OFF_SA   (OFF_BIAS + 512)
#define OFF_SW   (OFF_SA + 512)
#define SMEM_GEMM (OFF_SW + 512)
#define MAXTILES (T_TOK/TM + NE)     // 72
#define GATE_BLKS (T_TOK / 8)        // 1024
#define QMAX 32512.0f                // 127*256

// ---------------- device scratch ----------------
__device__ float g_gate_part[GATE_BLKS * NE];
__device__ int   g_top1[T_TOK];
__device__ int   g_cursor[NE];
__device__ int   g_perm[T_TOK];
__device__ int   g_tile_e[MAXTILES];
__device__ int   g_tile_row[MAXTILES];
__device__ int   g_tile_nrows[MAXTILES];
__device__ int   g_ntiles;

__device__ __align__(128) int8_t g_xqh[(T_TOK + TM) * D_IN];
__device__ __align__(128) int8_t g_xql[(T_TOK + TM) * D_IN];
__device__ float  g_xinv[T_TOK + TM];
__device__ __align__(128) int8_t g_wqh[NE * D_OUT * D_IN];
__device__ __align__(128) int8_t g_wql[NE * D_OUT * D_IN];
__device__ float  g_winv[NE * D_OUT];

// ---------------- helpers ----------------
__device__ __forceinline__ uint32_t smem_u32(const void* p) {
    return (uint32_t)__cvta_generic_to_shared(p);
}
__device__ __forceinline__ void cpa16(uint32_t dst, const void* src) {
    asm volatile("cp.async.cg.shared.global [%0], [%1], 16;\n" :: "r"(dst), "l"(src));
}
#define CP_COMMIT() asm volatile("cp.async.commit_group;" ::: "memory")
#define CP_WAIT(n)  asm volatile("cp.async.wait_group %0;" :: "n"(n) : "memory")

__device__ __forceinline__ void ldsm4(uint32_t* r, uint32_t a) {
    asm volatile("ldmatrix.sync.aligned.m8n8.x4.shared.b16 {%0,%1,%2,%3}, [%4];"
                 : "=r"(r[0]), "=r"(r[1]), "=r"(r[2]), "=r"(r[3]) : "r"(a));
}
__device__ __forceinline__ void mma_s8(int* c, const uint32_t* a, const uint32_t* b) {
    asm volatile("mma.sync.aligned.m16n8k32.row.col.s32.s8.s8.s32 "
                 "{%0,%1,%2,%3}, {%4,%5,%6,%7}, {%8,%9}, {%0,%1,%2,%3};"
                 : "+r"(c[0]), "+r"(c[1]), "+r"(c[2]), "+r"(c[3])
                 : "r"(a[0]), "r"(a[1]), "r"(a[2]), "r"(a[3]),
                   "r"(b[0]), "r"(b[1]));
}

// quantize 4 floats -> hi/lo int8 quads
__device__ __forceinline__ void quant4(float4 v, float s, char4& qh, char4& ql) {
    int q0 = __float2int_rn(v.x * s), q1 = __float2int_rn(v.y * s);
    int q2 = __float2int_rn(v.z * s), q3 = __float2int_rn(v.w * s);
    int l0 = (int)(int8_t)(q0 & 255), l1 = (int)(int8_t)(q1 & 255);
    int l2 = (int)(int8_t)(q2 & 255), l3 = (int)(int8_t)(q3 & 255);
    ql = make_char4((char)l0, (char)l1, (char)l2, (char)l3);
    qh = make_char4((char)((q0 - l0) >> 8), (char)((q1 - l1) >> 8),
                    (char)((q2 - l2) >> 8), (char)((q3 - l3) >> 8));
}

// ---------------- gate ----------------
__global__ void gate_kernel(const float* __restrict__ x,
                            const float* __restrict__ Wg,
                            const float* __restrict__ bg) {
    __shared__ float sWg[NE * D_IN];
    __shared__ float sSum[NE];
    int tid = threadIdx.x;
    for (int i = tid; i < NE * D_IN; i += blockDim.x) sWg[i] = Wg[i];
    if (tid < NE) sSum[tid] = 0.f;
    __syncthreads();

    int lane = tid & 31, warp = tid >> 5;
    int t = blockIdx.x * 8 + warp;

    float acc[NE];
#pragma unroll
    for (int e = 0; e < NE; e++) acc[e] = 0.f;
    const float* xp = x + (size_t)t * D_IN;
    for (int d = lane; d < D_IN; d += 32) {
        float xv = xp[d];
#pragma unroll
        for (int e = 0; e < NE; e++) acc[e] = fmaf(xv, sWg[e * D_IN + d], acc[e]);
    }
#pragma unroll
    for (int e = 0; e < NE; e++) {
#pragma unroll
        for (int o = 16; o; o >>= 1) acc[e] += __shfl_xor_sync(0xffffffffu, acc[e], o);
    }
    if (lane == 0) {
        float m = -1e30f; int am = 0;
#pragma unroll
        for (int e = 0; e < NE; e++) {
            acc[e] += bg[e];
            if (acc[e] > m) { m = acc[e]; am = e; }
        }
        float s = 0.f, p[NE];
#pragma unroll
        for (int e = 0; e < NE; e++) { p[e] = expf(acc[e] - m); s += p[e]; }
        float inv = 1.f / s;
        g_top1[t] = am;
#pragma unroll
        for (int e = 0; e < NE; e++) atomicAdd(&sSum[e], p[e] * inv);
    }
    __syncthreads();
    if (tid < NE) g_gate_part[blockIdx.x * NE + tid] = sSum[tid];
}

// ---------------- mid: histogram + tiles + cursors + aux ------------------
__global__ void mid_kernel(float* __restrict__ out_aux, int has_aux) {
    __shared__ int   hcnt[NE];
    __shared__ float ssum[NE];
    int tid = threadIdx.x;
    if (tid < NE) { hcnt[tid] = 0; ssum[tid] = 0.f; }
    __syncthreads();

    int lc[NE];
#pragma unroll
    for (int e = 0; e < NE; e++) lc[e] = 0;
    for (int t = tid; t < T_TOK; t += 256) lc[g_top1[t]]++;
#pragma unroll
    for (int e = 0; e < NE; e++) if (lc[e]) atomicAdd(&hcnt[e], lc[e]);

    float ls[NE];
#pragma unroll
    for (int e = 0; e < NE; e++) ls[e] = 0.f;
    for (int j = tid; j < GATE_BLKS; j += 256) {
#pragma unroll
        for (int e = 0; e < NE; e++) ls[e] += g_gate_part[j * NE + e];
    }
#pragma unroll
    for (int e = 0; e < NE; e++) {
#pragma unroll
        for (int o = 16; o; o >>= 1) ls[e] += __shfl_xor_sync(0xffffffffu, ls[e], o);
        if ((tid & 31) == 0) atomicAdd(&ssum[e], ls[e]);
    }
    __syncthreads();

    if (tid == 0) {
        int off = 0, n = 0;
        for (int e = 0; e < NE; e++) {
            g_cursor[e] = off;
            int c = hcnt[e];
            int nt = (c + TM - 1) / TM;
            for (int j = 0; j < nt; j++) {
                g_tile_e[n] = e;
                g_tile_row[n] = off + j * TM;
                int rem = c - j * TM;
                g_tile_nrows[n] = rem < TM ? rem : TM;
                n++;
            }
            off += c;
        }
        g_ntiles = n;
        if (has_aux) {
            float s = 0.f;
            for (int e = 0; e < NE; e++) {
                float mg = ssum[e] * (float)NE / (float)T_TOK;
                s += mg * mg;
            }
            *out_aux = s / (float)NE;
        }
    }
}

// ---------------- fused scatter + quantize x ------------------------------
__global__ void scatter_quant_kernel(const float* __restrict__ x) {
    int lane = threadIdx.x & 31, warp = threadIdx.x >> 5;
    int t = blockIdx.x * 8 + warp;
    int p;
    if (lane == 0) {
        int e = g_top1[t];
        p = atomicAdd(&g_cursor[e], 1);
        g_perm[p] = t;
    }
    p = __shfl_sync(0xffffffffu, p, 0);

    const float* xp = x + (size_t)t * D_IN;
    float4 v[8];
    float m = 0.f;
#pragma unroll
    for (int i = 0; i < 8; i++) {
        v[i] = *(const float4*)(xp + lane * 4 + i * 128);
        m = fmaxf(m, fmaxf(fmaxf(fabsf(v[i].x), fabsf(v[i].y)),
                           fmaxf(fabsf(v[i].z), fabsf(v[i].w))));
    }
#pragma unroll
    for (int o = 16; o; o >>= 1) m = fmaxf(m, __shfl_xor_sync(0xffffffffu, m, o));
    float s = (m > 0.f) ? (QMAX / m) : 0.f;
    if (lane == 0) g_xinv[p] = (m > 0.f) ? (m / QMAX) : 0.f;

    int8_t* oh = g_xqh + (size_t)p * D_IN;
    int8_t* ol = g_xql + (size_t)p * D_IN;
#pragma unroll
    for (int i = 0; i < 8; i++) {
        int d = lane * 4 + i * 128;
        char4 qh, ql;
        quant4(v[i], s, qh, ql);
        *(char4*)(oh + d) = qh;
        *(char4*)(ol + d) = ql;
    }
}

// ---------------- quantize We (per output row) ----------------------------
__global__ void quant_We_kernel(const float* __restrict__ We) {
    int lane = threadIdx.x & 31, warp = threadIdx.x >> 5;
    int rid = blockIdx.x * 8 + warp;          // 0 .. NE*D_OUT-1
    const float* wp = We + (size_t)rid * D_IN;
    float4 v[8];
    float m = 0.f;
#pragma unroll
    for (int i = 0; i < 8; i++) {
        v[i] = *(const float4*)(wp + lane * 4 + i * 128);
        m = fmaxf(m, fmaxf(fmaxf(fabsf(v[i].x), fabsf(v[i].y)),
                           fmaxf(fabsf(v[i].z), fabsf(v[i].w))));
    }
#pragma unroll
    for (int o = 16; o; o >>= 1) m = fmaxf(m, __shfl_xor_sync(0xffffffffu, m, o));
    float s = (m > 0.f) ? (QMAX / m) : 0.f;
    if (lane == 0) g_winv[rid] = (m > 0.f) ? (m / QMAX) : 0.f;

    int8_t* oh = g_wqh + (size_t)rid * D_IN;
    int8_t* ol = g_wql + (size_t)rid * D_IN;
#pragma unroll
    for (int i = 0; i < 8; i++) {
        int d = lane * 4 + i * 128;
        char4 qh, ql;
        quant4(v[i], s, qh, ql);
        *(char4*)(oh + d) = qh;
        *(char4*)(ol + d) = ql;
    }
}

// ---------------- expert GEMM: int8 3-pass IMMA ---------------------------
__global__ void __launch_bounds__(256, 1)
mma_gemm_kernel(const float* __restrict__ be, float* __restrict__ out) {
    int tile = blockIdx.y;
    if (tile >= g_ntiles) return;
    int e     = g_tile_e[tile];
    int row0  = g_tile_row[tile];
    int nrows = g_tile_nrows[tile];
    int o0    = blockIdx.x * TN;

    extern __shared__ char smem[];
    uint32_t sb = smem_u32(smem);
    int tid = threadIdx.x, l = tid & 31, wid = tid >> 5;
    int wm = wid & 3, wn = wid >> 2;

    int*   stok = (int*)(smem + OFF_STOK);
    float* bias = (float*)(smem + OFF_BIAS);
    float* s_sa = (float*)(smem + OFF_SA);
    float* s_sw = (float*)(smem + OFF_SW);
    if (tid < TM) {
        int r = tid < nrows ? tid : nrows - 1;
        stok[tid] = g_perm[row0 + r];
        s_sa[tid] = g_xinv[row0 + r];
        bias[tid] = be[e * D_OUT + o0 + tid];
        s_sw[tid] = g_winv[e * D_OUT + o0 + tid];
    }

    const int8_t* srcs[4];
    srcs[0] = g_xqh + (size_t)row0 * D_IN;
    srcs[1] = g_xql + (size_t)row0 * D_IN;
    srcs[2] = g_wqh + ((size_t)e * D_OUT + o0) * D_IN;
    srcs[3] = g_wql + ((size_t)e * D_OUT + o0) * D_IN;

    // loaders: 1024 x 16B chunks per stage, 4 per thread
    const int8_t* sp[4];
    uint32_t doff[4];
#pragma unroll
    for (int j = 0; j < 4; j++) {
        int c = tid + j * 256;
        int t4 = c >> 8;            // tile id
        int row = (c >> 1) & 127;
        int kc = c & 1;
        sp[j] = srcs[t4] + (size_t)row * D_IN + kc * 16;
        doff[j] = (uint32_t)(t4 * TILEB + row * ROWB + kc * 16);
    }

    auto load_stage = [&](int buf, int k0) {
        uint32_t base = sb + buf * STGB;
#pragma unroll
        for (int j = 0; j < 4; j++) cpa16(base + doff[j], sp[j] + k0);
    };

    uint32_t aOff = (uint32_t)((wm * 32 + (l & 15)) * ROWB + (l >> 4) * 16);
    uint32_t bOff = (uint32_t)(2 * TILEB + (wn * 64 + (l & 7) + ((l >> 4) & 1) * 8) * ROWB +
                               ((l >> 3) & 1) * 16);

    load_stage(0, 0);  CP_COMMIT();
    load_stage(1, BK); CP_COMMIT();

    int hh[2][8][4], mx[2][8][4];
#pragma unroll
    for (int mi = 0; mi < 2; mi++)
#pragma unroll
        for (int nj = 0; nj < 8; nj++)
#pragma unroll
            for (int q = 0; q < 4; q++) { hh[mi][nj][q] = 0; mx[mi][nj][q] = 0; }

    __syncthreads();

    for (int s = 0; s < KSTAGES; s++) {
        CP_WAIT(1);
        __syncthreads();
        if (s + 2 < KSTAGES) load_stage((s + 2) % NST, (s + 2) * BK);
        CP_COMMIT();

        uint32_t stb = sb + (s % NST) * STGB;
        uint32_t ah[2][4], al[2][4], bh[4][4], bl[4][4];
        uint32_t aB = stb + aOff;
        uint32_t bB = stb + bOff;
        ldsm4(ah[0], aB);
        ldsm4(ah[1], aB + 16 * ROWB);
        ldsm4(al[0], aB + TILEB);
        ldsm4(al[1], aB + TILEB + 16 * ROWB);
#pragma unroll
        for (int np = 0; np < 4; np++) {
            ldsm4(bh[np], bB + np * 16 * ROWB);
            ldsm4(bl[np], bB + TILEB + np * 16 * ROWB);
        }
#pragma unroll
        for (int mi = 0; mi < 2; mi++)
#pragma unroll
            for (int nj = 0; nj < 8; nj++) {
                mma_s8(hh[mi][nj], ah[mi], &bh[nj >> 1][(nj & 1) * 2]);
                mma_s8(mx[mi][nj], ah[mi], &bl[nj >> 1][(nj & 1) * 2]);
                mma_s8(mx[mi][nj], al[mi], &bh[nj >> 1][(nj & 1) * 2]);
            }
    }

    // epilogue: dequant + bias
    int g = l >> 2, t2 = (l & 3) * 2;
#pragma unroll
    for (int mi = 0; mi < 2; mi++) {
#pragma unroll
        for (int half = 0; half < 2; half++) {
            int row = wm * 32 + mi * 16 + g + half * 8;
            if (row < nrows) {
                float ra = s_sa[row];
                float* op = out + (size_t)stok[row] * D_OUT + o0;
#pragma unroll
                for (int nj = 0; nj < 8; nj++) {
                    int col = wn * 64 + nj * 8 + t2;
                    float c0 = 65536.f * (float)hh[mi][nj][half * 2 + 0] +
                                 256.f * (float)mx[mi][nj][half * 2 + 0];
                    float c1 = 65536.f * (float)hh[mi][nj][half * 2 + 1] +
                                 256.f * (float)mx[mi][nj][half * 2 + 1];
                    float2 v;
                    v.x = c0 * ra * s_sw[col]     + bias[col];
                    v.y = c1 * ra * s_sw[col + 1] + bias[col + 1];
                    *(float2*)(op + col) = v;
                }
            }
        }
    }
}

// ---------------- launch ----------------
extern "C" void kernel_launch(void* const* d_in, const int* in_sizes, int n_in,
                              void* d_out, int out_size) {
    const float* x  = (const float*)d_in[0];
    const float* We = (const float*)d_in[1];
    const float* be = (const float*)d_in[2];
    const float* Wg = (const float*)d_in[3];
    const float* bg = (const float*)d_in[4];
    float* out = (float*)d_out;

    cudaFuncSetAttribute(mma_gemm_kernel,
                         cudaFuncAttributeMaxDynamicSharedMemorySize, SMEM_GEMM);

    int has_aux = out_size > T_TOK * D_OUT;
    quant_We_kernel<<<NE * D_OUT / 8, 256>>>(We);
    gate_kernel<<<GATE_BLKS, 256>>>(x, Wg, bg);
    mid_kernel<<<1, 256>>>(out + (size_t)T_TOK * D_OUT, has_aux);
    scatter_quant_kernel<<<T_TOK / 8, 256>>>(x);
    dim3 grid(D_OUT / TN, MAXTILES);
    mma_gemm_kernel<<<grid, 256, SMEM_GEMM>>>(be, out);
}

// round 8
// speedup vs baseline: 2.4458x; 2.4458x over previous
#include <cuda_runtime.h>
#include <cuda_fp16.h>
#include <cstdint>

#define T_TOK 8192
#define D_IN  1024
#define D_OUT 1024
#define NE    8
#define TM    128
#define TN    128
#define BK    32
#define KSTAGES (D_IN / BK)          // 32
#define NST   3
#define ROWB  80                     // 32 fp16 = 64B + 16B pad (conflict-free)
#define TILEB (128 * ROWB)           // 10240
#define STGB  (3 * TILEB)            // 30720: Ah|Al|Bh
#define OFF_STOK (NST * STGB)        // 92160
#define OFF_BIAS (OFF_STOK + 512)
#define SMEM_GEMM (OFF_BIAS + 512)
#define MAXTILES (T_TOK/TM + NE)     // 72
#define GATE_BLKS (T_TOK / 8)        // 1024

// ---------------- device scratch ----------------
__device__ float g_gate_part[GATE_BLKS * NE];
__device__ int   g_top1[T_TOK];
__device__ int   g_cursor[NE];
__device__ int   g_perm[T_TOK];
__device__ int   g_tile_e[MAXTILES];
__device__ int   g_tile_row[MAXTILES];
__device__ int   g_tile_nrows[MAXTILES];
__device__ int   g_ntiles;

__device__ __align__(128) __half g_xh[(T_TOK + TM) * D_IN];
__device__ __align__(128) __half g_xl[(T_TOK + TM) * D_IN];
__device__ __align__(128) __half g_Wh[NE * D_OUT * D_IN];

// ---------------- helpers ----------------
__device__ __forceinline__ uint32_t smem_u32(const void* p) {
    return (uint32_t)__cvta_generic_to_shared(p);
}
__device__ __forceinline__ void cpa16(uint32_t dst, const void* src) {
    asm volatile("cp.async.cg.shared.global [%0], [%1], 16;\n" :: "r"(dst), "l"(src));
}
#define CP_COMMIT() asm volatile("cp.async.commit_group;" ::: "memory")
#define CP_WAIT(n)  asm volatile("cp.async.wait_group %0;" :: "n"(n) : "memory")

__device__ __forceinline__ void ldsm4(uint32_t* r, uint32_t a) {
    asm volatile("ldmatrix.sync.aligned.m8n8.x4.shared.b16 {%0,%1,%2,%3}, [%4];"
                 : "=r"(r[0]), "=r"(r[1]), "=r"(r[2]), "=r"(r[3]) : "r"(a));
}
__device__ __forceinline__ void mma_f16(float* c, const uint32_t* a, const uint32_t* b) {
    asm volatile("mma.sync.aligned.m16n8k16.row.col.f32.f16.f16.f32 "
                 "{%0,%1,%2,%3}, {%4,%5,%6,%7}, {%8,%9}, {%0,%1,%2,%3};"
                 : "+f"(c[0]), "+f"(c[1]), "+f"(c[2]), "+f"(c[3])
                 : "r"(a[0]), "r"(a[1]), "r"(a[2]), "r"(a[3]),
                   "r"(b[0]), "r"(b[1]));
}

// ---------------- gate ----------------
__global__ void gate_kernel(const float* __restrict__ x,
                            const float* __restrict__ Wg,
                            const float* __restrict__ bg) {
    __shared__ float sWg[NE * D_IN];
    __shared__ float sSum[NE];
    int tid = threadIdx.x;
    for (int i = tid; i < NE * D_IN; i += blockDim.x) sWg[i] = Wg[i];
    if (tid < NE) sSum[tid] = 0.f;
    __syncthreads();

    int lane = tid & 31, warp = tid >> 5;
    int t = blockIdx.x * 8 + warp;

    float acc[NE];
#pragma unroll
    for (int e = 0; e < NE; e++) acc[e] = 0.f;
    const float* xp = x + (size_t)t * D_IN;
    for (int d = lane; d < D_IN; d += 32) {
        float xv = xp[d];
#pragma unroll
        for (int e = 0; e < NE; e++) acc[e] = fmaf(xv, sWg[e * D_IN + d], acc[e]);
    }
#pragma unroll
    for (int e = 0; e < NE; e++) {
#pragma unroll
        for (int o = 16; o; o >>= 1) acc[e] += __shfl_xor_sync(0xffffffffu, acc[e], o);
    }
    if (lane == 0) {
        float m = -1e30f; int am = 0;
#pragma unroll
        for (int e = 0; e < NE; e++) {
            acc[e] += bg[e];
            if (acc[e] > m) { m = acc[e]; am = e; }
        }
        float s = 0.f, p[NE];
#pragma unroll
        for (int e = 0; e < NE; e++) { p[e] = expf(acc[e] - m); s += p[e]; }
        float inv = 1.f / s;
        g_top1[t] = am;
#pragma unroll
        for (int e = 0; e < NE; e++) atomicAdd(&sSum[e], p[e] * inv);
    }
    __syncthreads();
    if (tid < NE) g_gate_part[blockIdx.x * NE + tid] = sSum[tid];
}

// ---------------- mid: histogram + tiles + cursors + aux ------------------
__global__ void mid_kernel(float* __restrict__ out_aux, int has_aux) {
    __shared__ int   hcnt[NE];
    __shared__ float ssum[NE];
    int tid = threadIdx.x;
    if (tid < NE) { hcnt[tid] = 0; ssum[tid] = 0.f; }
    __syncthreads();

    int lc[NE];
#pragma unroll
    for (int e = 0; e < NE; e++) lc[e] = 0;
    for (int t = tid; t < T_TOK; t += 256) lc[g_top1[t]]++;
#pragma unroll
    for (int e = 0; e < NE; e++) if (lc[e]) atomicAdd(&hcnt[e], lc[e]);

    float ls[NE];
#pragma unroll
    for (int e = 0; e < NE; e++) ls[e] = 0.f;
    for (int j = tid; j < GATE_BLKS; j += 256) {
#pragma unroll
        for (int e = 0; e < NE; e++) ls[e] += g_gate_part[j * NE + e];
    }
#pragma unroll
    for (int e = 0; e < NE; e++) {
#pragma unroll
        for (int o = 16; o; o >>= 1) ls[e] += __shfl_xor_sync(0xffffffffu, ls[e], o);
        if ((tid & 31) == 0) atomicAdd(&ssum[e], ls[e]);
    }
    __syncthreads();

    if (tid == 0) {
        int off = 0, n = 0;
        for (int e = 0; e < NE; e++) {
            g_cursor[e] = off;
            int c = hcnt[e];
            int nt = (c + TM - 1) / TM;
            for (int j = 0; j < nt; j++) {
                g_tile_e[n] = e;
                g_tile_row[n] = off + j * TM;
                int rem = c - j * TM;
                g_tile_nrows[n] = rem < TM ? rem : TM;
                n++;
            }
            off += c;
        }
        g_ntiles = n;
        if (has_aux) {
            float s = 0.f;
            for (int e = 0; e < NE; e++) {
                float mg = ssum[e] * (float)NE / (float)T_TOK;
                s += mg * mg;
            }
            *out_aux = s / (float)NE;
        }
    }
}

// ---------------- fused scatter + gather-convert x (fp16 hi/lo) ----------
__global__ void scatter_convert_kernel(const float* __restrict__ x) {
    int lane = threadIdx.x & 31, warp = threadIdx.x >> 5;
    int t = blockIdx.x * 8 + warp;
    int p;
    if (lane == 0) {
        int e = g_top1[t];
        p = atomicAdd(&g_cursor[e], 1);
        g_perm[p] = t;
    }
    p = __shfl_sync(0xffffffffu, p, 0);

    const float* xp = x + (size_t)t * D_IN;
    __half* oh = g_xh + (size_t)p * D_IN;
    __half* ol = g_xl + (size_t)p * D_IN;
#pragma unroll
    for (int i = 0; i < 8; i++) {
        int d = lane * 4 + i * 128;
        float4 v = *(const float4*)(xp + d);
        __half h0 = __float2half(v.x), h1 = __float2half(v.y);
        __half h2 = __float2half(v.z), h3 = __float2half(v.w);
        __half l0 = __float2half(v.x - __half2float(h0));
        __half l1 = __float2half(v.y - __half2float(h1));
        __half l2 = __float2half(v.z - __half2float(h2));
        __half l3 = __float2half(v.w - __half2float(h3));
        *(__half2*)(oh + d)     = __halves2half2(h0, h1);
        *(__half2*)(oh + d + 2) = __halves2half2(h2, h3);
        *(__half2*)(ol + d)     = __halves2half2(l0, l1);
        *(__half2*)(ol + d + 2) = __halves2half2(l2, l3);
    }
}

// ---------------- convert We -> fp16 (hi only) ----------------------------
__global__ void convert_We_kernel(const float* __restrict__ We) {
    size_t stride = (size_t)gridDim.x * blockDim.x * 4;
    size_t total = (size_t)NE * D_OUT * D_IN;
    for (size_t i = (size_t)(blockIdx.x * blockDim.x + threadIdx.x) * 4; i < total; i += stride) {
        float4 v = *(const float4*)(We + i);
        *(__half2*)(g_Wh + i)     = __halves2half2(__float2half(v.x), __float2half(v.y));
        *(__half2*)(g_Wh + i + 2) = __halves2half2(__float2half(v.z), __float2half(v.w));
    }
}

// ---------------- expert GEMM: fp16 2-pass (A split), 1 sync/stage -------
__global__ void __launch_bounds__(256, 1)
mma_gemm_kernel(const float* __restrict__ be, float* __restrict__ out) {
    int tile = blockIdx.y;
    if (tile >= g_ntiles) return;
    int e     = g_tile_e[tile];
    int row0  = g_tile_row[tile];
    int nrows = g_tile_nrows[tile];
    int o0    = blockIdx.x * TN;

    extern __shared__ char smem[];
    uint32_t sb = smem_u32(smem);
    int tid = threadIdx.x, l = tid & 31, wid = tid >> 5;
    int wm = wid & 3, wn = wid >> 2;

    int*   stok = (int*)(smem + OFF_STOK);
    float* bias = (float*)(smem + OFF_BIAS);
    if (tid < TM) {
        int r = tid < nrows ? tid : nrows - 1;
        stok[tid] = g_perm[row0 + r];
        bias[tid] = be[e * D_OUT + o0 + tid];
    }

    const __half* srcs[3];
    srcs[0] = g_xh + (size_t)row0 * D_IN;
    srcs[1] = g_xl + (size_t)row0 * D_IN;
    srcs[2] = g_Wh + ((size_t)e * D_OUT + o0) * D_IN;

    // loaders: 3 tiles x 128 rows x 4 chunks = 1536 chunks, 6 per thread
    const __half* sp[6];
    uint32_t doff[6];
#pragma unroll
    for (int j = 0; j < 6; j++) {
        int c = tid + j * 256;
        int t3 = c >> 9;             // 0..2
        int row = (c >> 2) & 127;
        int kc = c & 3;
        sp[j] = srcs[t3] + (size_t)row * D_IN + kc * 8;
        doff[j] = (uint32_t)(t3 * TILEB + row * ROWB + kc * 16);
    }

    auto load_stage = [&](int buf, int k0) {
        uint32_t base = sb + buf * STGB;
#pragma unroll
        for (int j = 0; j < 6; j++) cpa16(base + doff[j], sp[j] + k0);
    };

    uint32_t aOff = (uint32_t)((wm * 32 + (l & 15)) * ROWB + ((l >> 4) & 1) * 16);
    uint32_t bOff = (uint32_t)(2 * TILEB + (wn * 64 + (l & 7) + ((l >> 4) & 1) * 8) * ROWB +
                               ((l >> 3) & 1) * 16);

    load_stage(0, 0);  CP_COMMIT();
    load_stage(1, BK); CP_COMMIT();

    float acc[2][8][4];
#pragma unroll
    for (int mi = 0; mi < 2; mi++)
#pragma unroll
        for (int nj = 0; nj < 8; nj++)
#pragma unroll
            for (int q = 0; q < 4; q++) acc[mi][nj][q] = 0.f;

    __syncthreads();

    for (int s = 0; s < KSTAGES; s++) {
        CP_WAIT(1);
        __syncthreads();
        if (s + 2 < KSTAGES) load_stage((s + 2) % NST, (s + 2) * BK);
        CP_COMMIT();

        uint32_t stb = sb + (s % NST) * STGB;
#pragma unroll
        for (int ks = 0; ks < 2; ks++) {
            uint32_t ah[2][4], al[2][4], bh[4][4];
            uint32_t aB = stb + aOff + ks * 32;
            uint32_t bB = stb + bOff + ks * 32;
            ldsm4(ah[0], aB);
            ldsm4(ah[1], aB + 16 * ROWB);
            ldsm4(al[0], aB + TILEB);
            ldsm4(al[1], aB + TILEB + 16 * ROWB);
#pragma unroll
            for (int np = 0; np < 4; np++)
                ldsm4(bh[np], bB + np * 16 * ROWB);
#pragma unroll
            for (int mi = 0; mi < 2; mi++)
#pragma unroll
                for (int nj = 0; nj < 8; nj++) {
                    mma_f16(acc[mi][nj], ah[mi], &bh[nj >> 1][(nj & 1) * 2]);
                    mma_f16(acc[mi][nj], al[mi], &bh[nj >> 1][(nj & 1) * 2]);
                }
        }
    }

    // epilogue
    int g = l >> 2, t2 = (l & 3) * 2;
#pragma unroll
    for (int mi = 0; mi < 2; mi++) {
#pragma unroll
        for (int half = 0; half < 2; half++) {
            int row = wm * 32 + mi * 16 + g + half * 8;
            if (row < nrows) {
                float* op = out + (size_t)stok[row] * D_OUT + o0;
#pragma unroll
                for (int nj = 0; nj < 8; nj++) {
                    int col = wn * 64 + nj * 8 + t2;
                    float2 v;
                    v.x = acc[mi][nj][half * 2 + 0] + bias[col];
                    v.y = acc[mi][nj][half * 2 + 1] + bias[col + 1];
                    *(float2*)(op + col) = v;
                }
            }
        }
    }
}

// ---------------- launch ----------------
extern "C" void kernel_launch(void* const* d_in, const int* in_sizes, int n_in,
                              void* d_out, int out_size) {
    const float* x  = (const float*)d_in[0];
    const float* We = (const float*)d_in[1];
    const float* be = (const float*)d_in[2];
    const float* Wg = (const float*)d_in[3];
    const float* bg = (const float*)d_in[4];
    float* out = (float*)d_out;

    cudaFuncSetAttribute(mma_gemm_kernel,
                         cudaFuncAttributeMaxDynamicSharedMemorySize, SMEM_GEMM);

    int has_aux = out_size > T_TOK * D_OUT;
    convert_We_kernel<<<4096, 256>>>(We);
    gate_kernel<<<GATE_BLKS, 256>>>(x, Wg, bg);
    mid_kernel<<<1, 256>>>(out + (size_t)T_TOK * D_OUT, has_aux);
    scatter_convert_kernel<<<T_TOK / 8, 256>>>(x);
    dim3 grid(D_OUT / TN, MAXTILES);
    mma_gemm_kernel<<<grid, 256, SMEM_GEMM>>>(be, out);
}

// round 11
// speedup vs baseline: 3.7744x; 1.5432x over previous
#include <cuda_runtime.h>
#include <cuda_fp16.h>
#include <cstdint>

#define T_TOK 8192
#define D_IN  1024
#define D_OUT 1024
#define NE    8
#define TM    128
#define TN    128
#define BK    32
#define KSTAGES (D_IN / BK)          // 32
#define NST   3
#define ROWB  80                     // 32 fp16 = 64B + 16B pad (conflict-free)
#define TILEB (128 * ROWB)           // 10240
#define STGB  (2 * TILEB)            // 20480: A|B
#define OFF_STOK (NST * STGB)        // 61440
#define OFF_BIAS (OFF_STOK + 512)
#define SMEM_GEMM (OFF_BIAS + 512)
#define MAXTILES (T_TOK/TM + NE)     // 72
#define GATE_BLKS (T_TOK / 8)        // 1024

// ---------------- device scratch ----------------
__device__ float g_gate_part[GATE_BLKS * NE];
__device__ int   g_top1[T_TOK];
__device__ int   g_cursor[NE];
__device__ int   g_perm[T_TOK];
__device__ int   g_tile_e[MAXTILES];
__device__ int   g_tile_row[MAXTILES];
__device__ int   g_tile_nrows[MAXTILES];
__device__ int   g_ntiles;

__device__ __align__(128) __half g_xh[(T_TOK + TM) * D_IN];
__device__ __align__(128) __half g_Wh[NE * D_OUT * D_IN];

// ---------------- helpers ----------------
__device__ __forceinline__ uint32_t smem_u32(const void* p) {
    return (uint32_t)__cvta_generic_to_shared(p);
}
__device__ __forceinline__ void cpa16(uint32_t dst, const void* src) {
    asm volatile("cp.async.cg.shared.global [%0], [%1], 16;\n" :: "r"(dst), "l"(src));
}
#define CP_COMMIT() asm volatile("cp.async.commit_group;" ::: "memory")
#define CP_WAIT(n)  asm volatile("cp.async.wait_group %0;" :: "n"(n) : "memory")

__device__ __forceinline__ void ldsm4(uint32_t* r, uint32_t a) {
    asm volatile("ldmatrix.sync.aligned.m8n8.x4.shared.b16 {%0,%1,%2,%3}, [%4];"
                 : "=r"(r[0]), "=r"(r[1]), "=r"(r[2]), "=r"(r[3]) : "r"(a));
}
__device__ __forceinline__ void mma_f16(float* c, const uint32_t* a, const uint32_t* b) {
    asm volatile("mma.sync.aligned.m16n8k16.row.col.f32.f16.f16.f32 "
                 "{%0,%1,%2,%3}, {%4,%5,%6,%7}, {%8,%9}, {%0,%1,%2,%3};"
                 : "+f"(c[0]), "+f"(c[1]), "+f"(c[2]), "+f"(c[3])
                 : "r"(a[0]), "r"(a[1]), "r"(a[2]), "r"(a[3]),
                   "r"(b[0]), "r"(b[1]));
}

// ---------------- gate ----------------
__global__ void gate_kernel(const float* __restrict__ x,
                            const float* __restrict__ Wg,
                            const float* __restrict__ bg) {
    __shared__ float sWg[NE * D_IN];
    __shared__ float sSum[NE];
    int tid = threadIdx.x;
    for (int i = tid; i < NE * D_IN; i += blockDim.x) sWg[i] = Wg[i];
    if (tid < NE) sSum[tid] = 0.f;
    __syncthreads();

    int lane = tid & 31, warp = tid >> 5;
    int t = blockIdx.x * 8 + warp;

    float acc[NE];
#pragma unroll
    for (int e = 0; e < NE; e++) acc[e] = 0.f;
    const float* xp = x + (size_t)t * D_IN;
    for (int d = lane; d < D_IN; d += 32) {
        float xv = xp[d];
#pragma unroll
        for (int e = 0; e < NE; e++) acc[e] = fmaf(xv, sWg[e * D_IN + d], acc[e]);
    }
#pragma unroll
    for (int e = 0; e < NE; e++) {
#pragma unroll
        for (int o = 16; o; o >>= 1) acc[e] += __shfl_xor_sync(0xffffffffu, acc[e], o);
    }
    if (lane == 0) {
        float m = -1e30f; int am = 0;
#pragma unroll
        for (int e = 0; e < NE; e++) {
            acc[e] += bg[e];
            if (acc[e] > m) { m = acc[e]; am = e; }
        }
        float s = 0.f, p[NE];
#pragma unroll
        for (int e = 0; e < NE; e++) { p[e] = expf(acc[e] - m); s += p[e]; }
        float inv = 1.f / s;
        g_top1[t] = am;
#pragma unroll
        for (int e = 0; e < NE; e++) atomicAdd(&sSum[e], p[e] * inv);
    }
    __syncthreads();
    if (tid < NE) g_gate_part[blockIdx.x * NE + tid] = sSum[tid];
}

// ---------------- mid: histogram + tiles + cursors + aux ------------------
__global__ void mid_kernel(float* __restrict__ out_aux, int has_aux) {
    __shared__ int   hcnt[NE];
    __shared__ float ssum[NE];
    int tid = threadIdx.x;
    if (tid < NE) { hcnt[tid] = 0; ssum[tid] = 0.f; }
    __syncthreads();

    int lc[NE];
#pragma unroll
    for (int e = 0; e < NE; e++) lc[e] = 0;
    for (int t = tid; t < T_TOK; t += 256) lc[g_top1[t]]++;
#pragma unroll
    for (int e = 0; e < NE; e++) if (lc[e]) atomicAdd(&hcnt[e], lc[e]);

    float ls[NE];
#pragma unroll
    for (int e = 0; e < NE; e++) ls[e] = 0.f;
    for (int j = tid; j < GATE_BLKS; j += 256) {
#pragma unroll
        for (int e = 0; e < NE; e++) ls[e] += g_gate_part[j * NE + e];
    }
#pragma unroll
    for (int e = 0; e < NE; e++) {
#pragma unroll
        for (int o = 16; o; o >>= 1) ls[e] += __shfl_xor_sync(0xffffffffu, ls[e], o);
        if ((tid & 31) == 0) atomicAdd(&ssum[e], ls[e]);
    }
    __syncthreads();

    if (tid == 0) {
        int off = 0, n = 0;
        for (int e = 0; e < NE; e++) {
            g_cursor[e] = off;
            int c = hcnt[e];
            int nt = (c + TM - 1) / TM;
            for (int j = 0; j < nt; j++) {
                g_tile_e[n] = e;
                g_tile_row[n] = off + j * TM;
                int rem = c - j * TM;
                g_tile_nrows[n] = rem < TM ? rem : TM;
                n++;
            }
            off += c;
        }
        g_ntiles = n;
        if (has_aux) {
            float s = 0.f;
            for (int e = 0; e < NE; e++) {
                float mg = ssum[e] * (float)NE / (float)T_TOK;
                s += mg * mg;
            }
            *out_aux = s / (float)NE;
        }
    }
}

// ---------------- fused scatter + gather-convert x (fp16) ----------------
__global__ void scatter_convert_kernel(const float* __restrict__ x) {
    int lane = threadIdx.x & 31, warp = threadIdx.x >> 5;
    int t = blockIdx.x * 8 + warp;
    int p;
    if (lane == 0) {
        int e = g_top1[t];
        p = atomicAdd(&g_cursor[e], 1);
        g_perm[p] = t;
    }
    p = __shfl_sync(0xffffffffu, p, 0);

    const float* xp = x + (size_t)t * D_IN;
    __half* oh = g_xh + (size_t)p * D_IN;
#pragma unroll
    for (int i = 0; i < 8; i++) {
        int d = lane * 4 + i * 128;
        float4 v = *(const float4*)(xp + d);
        *(__half2*)(oh + d)     = __halves2half2(__float2half(v.x), __float2half(v.y));
        *(__half2*)(oh + d + 2) = __halves2half2(__float2half(v.z), __float2half(v.w));
    }
}

// ---------------- convert We -> fp16 ----------------------------
__global__ void convert_We_kernel(const float* __restrict__ We) {
    size_t stride = (size_t)gridDim.x * blockDim.x * 4;
    size_t total = (size_t)NE * D_OUT * D_IN;
    for (size_t i = (size_t)(blockIdx.x * blockDim.x + threadIdx.x) * 4; i < total; i += stride) {
        float4 v = *(const float4*)(We + i);
        *(__half2*)(g_Wh + i)     = __halves2half2(__float2half(v.x), __float2half(v.y));
        *(__half2*)(g_Wh + i + 2) = __halves2half2(__float2half(v.z), __float2half(v.w));
    }
}

// ---------------- expert GEMM: fp16 1-pass, 1 sync/stage, occ 2 ----------
__global__ void __launch_bounds__(256, 2)
mma_gemm_kernel(const float* __restrict__ be, float* __restrict__ out) {
    int tile = blockIdx.y;
    if (tile >= g_ntiles) return;
    int e     = g_tile_e[tile];
    int row0  = g_tile_row[tile];
    int nrows = g_tile_nrows[tile];
    int o0    = blockIdx.x * TN;

    extern __shared__ char smem[];
    uint32_t sb = smem_u32(smem);
    int tid = threadIdx.x, l = tid & 31, wid = tid >> 5;
    int wm = wid & 3, wn = wid >> 2;

    int*   stok = (int*)(smem + OFF_STOK);
    float* bias = (float*)(smem + OFF_BIAS);
    if (tid < TM) {
        int r = tid < nrows ? tid : nrows - 1;
        stok[tid] = g_perm[row0 + r];
        bias[tid] = be[e * D_OUT + o0 + tid];
    }

    const __half* srcs[2];
    srcs[0] = g_xh + (size_t)row0 * D_IN;
    srcs[1] = g_Wh + ((size_t)e * D_OUT + o0) * D_IN;

    // loaders: 2 tiles x 128 rows x 4 chunks = 1024 chunks, 4 per thread
    const __half* sp[4];
    uint32_t doff[4];
#pragma unroll
    for (int j = 0; j < 4; j++) {
        int c = tid + j * 256;
        int t2i = c >> 9;            // 0..1
        int row = (c >> 2) & 127;
        int kc = c & 3;
        sp[j] = srcs[t2i] + (size_t)row * D_IN + kc * 8;
        doff[j] = (uint32_t)(t2i * TILEB + row * ROWB + kc * 16);
    }

    auto load_stage = [&](int buf, int k0) {
        uint32_t base = sb + buf * STGB;
#pragma unroll
        for (int j = 0; j < 4; j++) cpa16(base + doff[j], sp[j] + k0);
    };

    uint32_t aOff = (uint32_t)((wm * 32 + (l & 15)) * ROWB + ((l >> 4) & 1) * 16);
    uint32_t bOff = (uint32_t)(TILEB + (wn * 64 + (l & 7) + ((l >> 4) & 1) * 8) * ROWB +
                               ((l >> 3) & 1) * 16);

    load_stage(0, 0);  CP_COMMIT();
    load_stage(1, BK); CP_COMMIT();

    float acc[2][8][4];
#pragma unroll
    for (int mi = 0; mi < 2; mi++)
#pragma unroll
        for (int nj = 0; nj < 8; nj++)
#pragma unroll
            for (int q = 0; q < 4; q++) acc[mi][nj][q] = 0.f;

    __syncthreads();

    for (int s = 0; s < KSTAGES; s++) {
        CP_WAIT(1);
        __syncthreads();
        if (s + 2 < KSTAGES) load_stage((s + 2) % NST, (s + 2) * BK);
        CP_COMMIT();

        uint32_t stb = sb + (s % NST) * STGB;
#pragma unroll
        for (int ks = 0; ks < 2; ks++) {
            uint32_t ah[2][4], bh[4][4];
            uint32_t aB = stb + aOff + ks * 32;
            uint32_t bB = stb + bOff + ks * 32;
            ldsm4(ah[0], aB);
            ldsm4(ah[1], aB + 16 * ROWB);
#pragma unroll
            for (int np = 0; np < 4; np++)
                ldsm4(bh[np], bB + np * 16 * ROWB);
#pragma unroll
            for (int mi = 0; mi < 2; mi++)
#pragma unroll
                for (int nj = 0; nj < 8; nj++)
                    mma_f16(acc[mi][nj], ah[mi], &bh[nj >> 1][(nj & 1) * 2]);
        }
    }

    // epilogue
    int g = l >> 2, t2 = (l & 3) * 2;
#pragma unroll
    for (int mi = 0; mi < 2; mi++) {
#pragma unroll
        for (int half = 0; half < 2; half++) {
            int row = wm * 32 + mi * 16 + g + half * 8;
            if (row < nrows) {
                float* op = out + (size_t)stok[row] * D_OUT + o0;
#pragma unroll
                for (int nj = 0; nj < 8; nj++) {
                    int col = wn * 64 + nj * 8 + t2;
                    float2 v;
                    v.x = acc[mi][nj][half * 2 + 0] + bias[col];
                    v.y = acc[mi][nj][half * 2 + 1] + bias[col + 1];
                    *(float2*)(op + col) = v;
                }
            }
        }
    }
}

// ---------------- launch ----------------
extern "C" void kernel_launch(void* const* d_in, const int* in_sizes, int n_in,
                              void* d_out, int out_size) {
    const float* x  = (const float*)d_in[0];
    const float* We = (const float*)d_in[1];
    const float* be = (const float*)d_in[2];
    const float* Wg = (const float*)d_in[3];
    const float* bg = (const float*)d_in[4];
    float* out = (float*)d_out;

    cudaFuncSetAttribute(mma_gemm_kernel,
                         cudaFuncAttributeMaxDynamicSharedMemorySize, SMEM_GEMM);

    int has_aux = out_size > T_TOK * D_OUT;
    convert_We_kernel<<<4096, 256>>>(We);
    gate_kernel<<<GATE_BLKS, 256>>>(x, Wg, bg);
    mid_kernel<<<1, 256>>>(out + (size_t)T_TOK * D_OUT, has_aux);
    scatter_convert_kernel<<<T_TOK / 8, 256>>>(x);
    dim3 grid(D_OUT / TN, MAXTILES);
    mma_gemm_kernel<<<grid, 256, SMEM_GEMM>>>(be, out);
}

// round 13
// speedup vs baseline: 3.8372x; 1.0166x over previous
#include <cuda_runtime.h>
#include <cuda_fp16.h>
#include <cstdint>

#define T_TOK 8192
#define D_IN  1024
#define D_OUT 1024
#define NE    8
#define TM    128
#define TN    128
#define BK    32
#define KSTAGES (D_IN / BK)          // 32
#define NST   3
#define ROWB  80                     // 32 fp16 = 64B + 16B pad (conflict-free)
#define TILEB (128 * ROWB)           // 10240
#define STGB  (2 * TILEB)            // 20480: A|B
#define OFF_STOK (NST * STGB)        // 61440
#define OFF_BIAS (OFF_STOK + 512)
#define SMEM_GEMM (OFF_BIAS + 512)
#define MAXTILES (T_TOK/TM + NE)     // 72
#define GATE_BLKS (T_TOK / 8)        // 1024
#define CONV_BLKS 1024

// ---------------- device scratch ----------------
__device__ float g_gate_part[GATE_BLKS * NE];
__device__ int   g_top1[T_TOK];
__device__ int   g_perm[T_TOK];
__device__ int   g_tile_e[MAXTILES];
__device__ int   g_tile_row[MAXTILES];
__device__ int   g_tile_nrows[MAXTILES];
__device__ int   g_ntiles;

__device__ __align__(128) __half g_xh[T_TOK * D_IN];
__device__ __align__(128) __half g_Wh[NE * D_OUT * D_IN];

// ---------------- helpers ----------------
__device__ __forceinline__ uint32_t smem_u32(const void* p) {
    return (uint32_t)__cvta_generic_to_shared(p);
}
__device__ __forceinline__ void cpa16(uint32_t dst, const void* src) {
    asm volatile("cp.async.cg.shared.global [%0], [%1], 16;\n" :: "r"(dst), "l"(src));
}
#define CP_COMMIT() asm volatile("cp.async.commit_group;" ::: "memory")
#define CP_WAIT(n)  asm volatile("cp.async.wait_group %0;" :: "n"(n) : "memory")

__device__ __forceinline__ void ldsm4(uint32_t* r, uint32_t a) {
    asm volatile("ldmatrix.sync.aligned.m8n8.x4.shared.b16 {%0,%1,%2,%3}, [%4];"
                 : "=r"(r[0]), "=r"(r[1]), "=r"(r[2]), "=r"(r[3]) : "r"(a));
}
__device__ __forceinline__ void mma_f16(float* c, const uint32_t* a, const uint32_t* b) {
    asm volatile("mma.sync.aligned.m16n8k16.row.col.f32.f16.f16.f32 "
                 "{%0,%1,%2,%3}, {%4,%5,%6,%7}, {%8,%9}, {%0,%1,%2,%3};"
                 : "+f"(c[0]), "+f"(c[1]), "+f"(c[2]), "+f"(c[3])
                 : "r"(a[0]), "r"(a[1]), "r"(a[2]), "r"(a[3]),
                   "r"(b[0]), "r"(b[1]));
}

// ---------------- fused: gate(+x convert) | We convert -------------------
__global__ void gate_conv_kernel(const float* __restrict__ x,
                                 const float* __restrict__ Wg,
                                 const float* __restrict__ bg,
                                 const float* __restrict__ We) {
    int tid = threadIdx.x;

    if (blockIdx.x >= GATE_BLKS) {
        // ---- We -> fp16 convert part ----
        size_t base = ((size_t)(blockIdx.x - GATE_BLKS) * 256 + tid) * 4;
        size_t stride = (size_t)CONV_BLKS * 256 * 4;
#pragma unroll
        for (int i = 0; i < 8; i++) {
            size_t idx = base + (size_t)i * stride;
            float4 v = *(const float4*)(We + idx);
            *(__half2*)(g_Wh + idx)     = __halves2half2(__float2half(v.x), __float2half(v.y));
            *(__half2*)(g_Wh + idx + 2) = __halves2half2(__float2half(v.z), __float2half(v.w));
        }
        return;
    }

    // ---- gate part: 8 tokens per block (one per warp) ----
    __shared__ float sWg[NE * D_IN];
    __shared__ float sSum[NE];
    for (int i = tid; i < NE * D_IN; i += blockDim.x) sWg[i] = Wg[i];
    if (tid < NE) sSum[tid] = 0.f;
    __syncthreads();

    int lane = tid & 31, warp = tid >> 5;
    int t = blockIdx.x * 8 + warp;

    float acc[NE];
#pragma unroll
    for (int e = 0; e < NE; e++) acc[e] = 0.f;
    const float* xp = x + (size_t)t * D_IN;
    for (int d = lane; d < D_IN; d += 32) {
        float xv = xp[d];
#pragma unroll
        for (int e = 0; e < NE; e++) acc[e] = fmaf(xv, sWg[e * D_IN + d], acc[e]);
    }
#pragma unroll
    for (int e = 0; e < NE; e++) {
#pragma unroll
        for (int o = 16; o; o >>= 1) acc[e] += __shfl_xor_sync(0xffffffffu, acc[e], o);
    }
    if (lane == 0) {
        float m = -1e30f; int am = 0;
#pragma unroll
        for (int e = 0; e < NE; e++) {
            acc[e] += bg[e];
            if (acc[e] > m) { m = acc[e]; am = e; }
        }
        float s = 0.f, p[NE];
#pragma unroll
        for (int e = 0; e < NE; e++) { p[e] = expf(acc[e] - m); s += p[e]; }
        float inv = 1.f / s;
        g_top1[t] = am;
#pragma unroll
        for (int e = 0; e < NE; e++) atomicAdd(&sSum[e], p[e] * inv);
    }

    // ---- convert this token's row to fp16 (x row is L1-hot) ----
    __half* oh = g_xh + (size_t)t * D_IN;
#pragma unroll
    for (int i = 0; i < 8; i++) {
        int d = lane * 4 + i * 128;
        float4 v = *(const float4*)(xp + d);
        *(__half2*)(oh + d)     = __halves2half2(__float2half(v.x), __float2half(v.y));
        *(__half2*)(oh + d + 2) = __halves2half2(__float2half(v.z), __float2half(v.w));
    }

    __syncthreads();
    if (tid < NE) g_gate_part[blockIdx.x * NE + tid] = sSum[tid];
}

// ---------------- mid: histogram + tiles + aux + atomic-free scatter -----
__global__ void mid_kernel(float* __restrict__ out_aux, int has_aux) {
    __shared__ int   lcnt[256][NE];    // 8 KB
    __shared__ int   hcnt[NE];
    __shared__ int   cur0[NE];
    __shared__ float ssum[NE];
    int tid = threadIdx.x;
    if (tid < NE) ssum[tid] = 0.f;

    // local histogram over strided tokens
    int lc[NE];
#pragma unroll
    for (int e = 0; e < NE; e++) lc[e] = 0;
    for (int t = tid; t < T_TOK; t += 256) lc[g_top1[t]]++;
#pragma unroll
    for (int e = 0; e < NE; e++) lcnt[tid][e] = lc[e];

    // gate prob sums for aux
    float ls[NE];
#pragma unroll
    for (int e = 0; e < NE; e++) ls[e] = 0.f;
    for (int j = tid; j < GATE_BLKS; j += 256) {
#pragma unroll
        for (int e = 0; e < NE; e++) ls[e] += g_gate_part[j * NE + e];
    }
#pragma unroll
    for (int e = 0; e < NE; e++) {
#pragma unroll
        for (int o = 16; o; o >>= 1) ls[e] += __shfl_xor_sync(0xffffffffu, ls[e], o);
        if ((tid & 31) == 0) atomicAdd(&ssum[e], ls[e]);
    }
    __syncthreads();

    // per-expert exclusive scan over the 256 thread counts (8 threads, serial)
    if (tid < NE) {
        int run = 0;
        for (int i = 0; i < 256; i++) {
            int v = lcnt[i][tid];
            lcnt[i][tid] = run;
            run += v;
        }
        hcnt[tid] = run;
    }
    __syncthreads();

    if (tid == 0) {
        int off = 0, n = 0;
        for (int e = 0; e < NE; e++) {
            cur0[e] = off;
            int c = hcnt[e];
            int nt = (c + TM - 1) / TM;
            for (int j = 0; j < nt; j++) {
                g_tile_e[n] = e;
                g_tile_row[n] = off + j * TM;
                int rem = c - j * TM;
                g_tile_nrows[n] = rem < TM ? rem : TM;
                n++;
            }
            off += c;
        }
        g_ntiles = n;
        if (has_aux) {
            float s = 0.f;
            for (int e = 0; e < NE; e++) {
                float mg = ssum[e] * (float)NE / (float)T_TOK;
                s += mg * mg;
            }
            *out_aux = s / (float)NE;
        }
    }
    __syncthreads();

    // deterministic scatter: this thread's slots start at cur0[e] + lcnt[tid][e]
    int ofs[NE];
#pragma unroll
    for (int e = 0; e < NE; e++) ofs[e] = cur0[e] + lcnt[tid][e];
    for (int t = tid; t < T_TOK; t += 256) {
        int e = g_top1[t];
        g_perm[ofs[e]++] = t;
    }
}

// ---------------- expert GEMM: fp16 1-pass, perm-indirect A loads --------
__global__ void __launch_bounds__(256, 2)
mma_gemm_kernel(const float* __restrict__ be, float* __restrict__ out) {
    int tile = blockIdx.y;
    if (tile >= g_ntiles) return;
    int e     = g_tile_e[tile];
    int row0  = g_tile_row[tile];
    int nrows = g_tile_nrows[tile];
    int o0    = blockIdx.x * TN;

    extern __shared__ char smem[];
    uint32_t sb = smem_u32(smem);
    int tid = threadIdx.x, l = tid & 31, wid = tid >> 5;
    int wm = wid & 3, wn = wid >> 2;

    int*   stok = (int*)(smem + OFF_STOK);
    float* bias = (float*)(smem + OFF_BIAS);
    if (tid < TM) {
        int r = tid < nrows ? tid : nrows - 1;
        stok[tid] = g_perm[row0 + r];
        bias[tid] = be[e * D_OUT + o0 + tid];
    }

    // loaders: 2 tiles x 128 rows x 4 chunks = 1024 chunks, 4 per thread
    // A chunks (j=0,1) read via perm indirection into unpermuted g_xh
    const __half* sp[4];
    uint32_t doff[4];
#pragma unroll
    for (int j = 0; j < 4; j++) {
        int c = tid + j * 256;
        int t2i = c >> 9;            // 0..1
        int row = (c >> 2) & 127;
        int kc = c & 3;
        if (t2i == 0) {
            int rr = row < nrows ? row : nrows - 1;
            sp[j] = g_xh + (size_t)g_perm[row0 + rr] * D_IN + kc * 8;
        } else {
            sp[j] = g_Wh + ((size_t)e * D_OUT + o0 + row) * D_IN + kc * 8;
        }
        doff[j] = (uint32_t)(t2i * TILEB + row * ROWB + kc * 16);
    }

    auto load_stage = [&](int buf, int k0) {
        uint32_t base = sb + buf * STGB;
#pragma unroll
        for (int j = 0; j < 4; j++) cpa16(base + doff[j], sp[j] + k0);
    };

    uint32_t aOff = (uint32_t)((wm * 32 + (l & 15)) * ROWB + ((l >> 4) & 1) * 16);
    uint32_t bOff = (uint32_t)(TILEB + (wn * 64 + (l & 7) + ((l >> 4) & 1) * 8) * ROWB +
                               ((l >> 3) & 1) * 16);

    load_stage(0, 0);  CP_COMMIT();
    load_stage(1, BK); CP_COMMIT();

    float acc[2][8][4];
#pragma unroll
    for (int mi = 0; mi < 2; mi++)
#pragma unroll
        for (int nj = 0; nj < 8; nj++)
#pragma unroll
            for (int q = 0; q < 4; q++) acc[mi][nj][q] = 0.f;

    __syncthreads();

    for (int s = 0; s < KSTAGES; s++) {
        CP_WAIT(1);
        __syncthreads();
        if (s + 2 < KSTAGES) load_stage((s + 2) % NST, (s + 2) * BK);
        CP_COMMIT();

        uint32_t stb = sb + (s % NST) * STGB;
#pragma unroll
        for (int ks = 0; ks < 2; ks++) {
            uint32_t ah[2][4], bh[4][4];
            uint32_t aB = stb + aOff + ks * 32;
            uint32_t bB = stb + bOff + ks * 32;
            ldsm4(ah[0], aB);
            ldsm4(ah[1], aB + 16 * ROWB);
#pragma unroll
            for (int np = 0; np < 4; np++)
                ldsm4(bh[np], bB + np * 16 * ROWB);
#pragma unroll
            for (int mi = 0; mi < 2; mi++)
#pragma unroll
                for (int nj = 0; nj < 8; nj++)
                    mma_f16(acc[mi][nj], ah[mi], &bh[nj >> 1][(nj & 1) * 2]);
        }
    }

    // epilogue
    int g = l >> 2, t2 = (l & 3) * 2;
#pragma unroll
    for (int mi = 0; mi < 2; mi++) {
#pragma unroll
        for (int half = 0; half < 2; half++) {
            int row = wm * 32 + mi * 16 + g + half * 8;
            if (row < nrows) {
                float* op = out + (size_t)stok[row] * D_OUT + o0;
#pragma unroll
                for (int nj = 0; nj < 8; nj++) {
                    int col = wn * 64 + nj * 8 + t2;
                    float2 v;
                    v.x = acc[mi][nj][half * 2 + 0] + bias[col];
                    v.y = acc[mi][nj][half * 2 + 1] + bias[col + 1];
                    *(float2*)(op + col) = v;
                }
            }
        }
    }
}

// ---------------- launch ----------------
extern "C" void kernel_launch(void* const* d_in, const int* in_sizes, int n_in,
                              void* d_out, int out_size) {
    const float* x  = (const float*)d_in[0];
    const float* We = (const float*)d_in[1];
    const float* be = (const float*)d_in[2];
    const float* Wg = (const float*)d_in[3];
    const float* bg = (const float*)d_in[4];
    float* out = (float*)d_out;

    cudaFuncSetAttribute(mma_gemm_kernel,
                         cudaFuncAttributeMaxDynamicSharedMemorySize, SMEM_GEMM);

    int has_aux = out_size > T_TOK * D_OUT;
    gate_conv_kernel<<<GATE_BLKS + CONV_BLKS, 256>>>(x, Wg, bg, We);
    mid_kernel<<<1, 256>>>(out + (size_t)T_TOK * D_OUT, has_aux);
    dim3 grid(D_OUT / TN, MAXTILES);
    mma_gemm_kernel<<<grid, 256, SMEM_GEMM>>>(be, out);
}